// round 14
// baseline (speedup 1.0000x reference)
#include <cuda_runtime.h>
#include <math.h>

#define POOL 7
#define ROI_SCALE 0.0625f
#define WPB 8        // warps per block
#define CH  8        // channels per warp
#define NGR 32       // channel groups = C/CH
#define CMW 68       // smem row pitch in floats (16B-aligned)
#define TPR (NGR * 4)     // warp-tasks per ROI: 32 groups x 4 bin-pairs

// Fully unrolled segment max: psx is warp-uniform (<=10 since lenx<=64).
// Guards keep stale smem (cols outside the written range) out of the max.
template<int PSX>
__device__ __forceinline__ float segmax(const float* rp, int i0, int i1,
                                        float init) {
    float mm = init;
    #pragma unroll
    for (int i = 0; i < PSX; ++i)
        if (i >= i0 && i < i1) mm = fmaxf(mm, rp[i]);
    return mm;
}

// grid = (TPR/WPB, N) = (16, N). Block owns one ROI (geometry decoded once by
// thread 0 into smem). Warp task = (8-channel group, pair of row-bins:
// {0,1},{2,3},{4,5},{6}). Lanes: h=lane>>4 picks plane parity, li=lane&15
// covers 64 cols as float4 -> 4 LDG.128/row for 8 planes, 2-row unrolled.
// Per bin: flush 4xSTS.128 to 2KB/warp smem; each lane reduces 2 of the 56
// (ch,pw) outputs via an unrolled warp-uniform segmented max.
__global__ __launch_bounds__(32 * WPB, 6)
void roipool_kernel(const float* __restrict__ feat,
                    const float* __restrict__ rois,
                    float* __restrict__ out,
                    int N, int C, int write_bid) {
    __shared__ float cm[WPB][CH * CMW];
    __shared__ int g[10];   // b,px,py,qx, lenx,leny, psx,psy, pad0x,pad0y
    const int H = 64, W = 64;

    int n = blockIdx.y;

    // Fused second output of the reference tuple: batch ids as floats.
    if (write_bid && blockIdx.x == 0 && blockIdx.y == 0 && threadIdx.x < N) {
        out[N * C * POOL * POOL + threadIdx.x] =
            (float)((int)rois[threadIdx.x * 5]);
    }

    if (threadIdx.x == 0) {
        const float* r = rois + n * 5;
        // jnp.round = round-half-to-even = __float2int_rn
        int px = __float2int_rn(r[1] * ROI_SCALE);
        int py = __float2int_rn(r[2] * ROI_SCALE);
        int qx = __float2int_rn(r[3] * ROI_SCALE);
        int qy = __float2int_rn(r[4] * ROI_SCALE);
        int lenx = max(qx - px + 1, 1);
        int leny = max(qy - py + 1, 1);
        int psx  = (lenx + POOL - 1) / POOL;
        int psy  = (leny + POOL - 1) / POOL;
        g[0] = (int)r[0];
        g[1] = px; g[2] = py; g[3] = qx;
        g[4] = lenx; g[5] = leny;
        g[6] = psx; g[7] = psy;
        g[8] = (psx * POOL - lenx) / 2;
        g[9] = (psy * POOL - leny) / 2;
    }
    __syncthreads();

    int warp = threadIdx.x >> 5;
    int lane = threadIdx.x & 31;
    int task = blockIdx.x * WPB + warp;   // 0..TPR-1
    int cg   = task & (NGR - 1);          // channel group (8 channels)
    int pr   = task >> 5;                 // bin pair 0..3
    int ph0  = 2 * pr;
    int nb   = (pr < 3) ? 2 : 1;          // bins in this task

    int psy = g[7], pad0y = g[9], leny = g[5];
    int lenx = g[4], psx = g[6], pad0x = g[8];

    // ---- lane load config ----
    int h  = lane >> 4;                   // plane parity
    int li = lane & 15;                   // float4 column index
    int px4 = g[1] & ~3;                  // 16B-aligned load base
    int dpx = g[1] - px4;                 // 0..3
    bool act = (px4 + 4 * li) <= g[3];
    const float* bp = feat
        + (unsigned)((g[0] * C + cg * CH + h) * (H * W))
        + (unsigned)(g[2] * W + px4 + 4 * li);

    // ---- ph-invariant reduce roles: lane owns outputs lane and lane+32 ----
    float* cw = cm[warp];
    int ch0 = lane / POOL, pw0 = lane - ch0 * POOL;   // const-div -> mul
    int bi1 = lane + 32;
    int ch1 = bi1 / POOL, pw1 = bi1 - ch1 * POOL;
    bool r1 = bi1 < CH * POOL;
    int x00 = pw0 * psx - pad0x;
    int i00 = max(0, -x00), i01 = min(psx, lenx - x00);
    int x10 = pw1 * psx - pad0x;
    int i10 = max(0, -x10), i11 = min(psx, lenx - x10);
    bool padx0 = (pw0 * psx < pad0x) | ((pw0 + 1) * psx > pad0x + lenx);
    bool padx1 = (pw1 * psx < pad0x) | ((pw1 + 1) * psx > pad0x + lenx);
    const float* rp0 = cw + ch0 * CMW + x00 + dpx;
    const float* rp1 = cw + ch1 * CMW + x10 + dpx;
    int o0 = (n * C + cg * CH + ch0) * (POOL * POOL) + pw0;
    int o1 = (n * C + cg * CH + ch1) * (POOL * POOL) + pw1;

#define FM4(d, s) d.x = fmaxf(d.x, s.x); d.y = fmaxf(d.y, s.y); \
                  d.z = fmaxf(d.z, s.z); d.w = fmaxf(d.w, s.w)
#define LD4(q, off) __ldg((const float4*)((q) + (off)))

    for (int k = 0; k < nb; ++k) {
        int ph = ph0 + k;
        int ys = max(0, ph * psy - pad0y);
        int ye = min(leny - 1, (ph + 1) * psy - 1 - pad0y);

        if (ys > ye) {                    // fully zero-padded row bin -> 0
            out[o0 + ph * POOL] = 0.0f;
            if (r1) out[o1 + ph * POOL] = 0.0f;
            continue;                     // warp-uniform
        }

        float4 a0 = make_float4(-INFINITY, -INFINITY, -INFINITY, -INFINITY);
        float4 a1 = a0, a2 = a0, a3 = a0;

        const float* p = bp + ys * W;
        int ry = ys;
        for (; ry + 1 <= ye; ry += 2) {   // 8 LDG.128 in flight
            if (act) {
                float4 u0 = LD4(p, 0);
                float4 u1 = LD4(p, 2 * H * W);
                float4 u2 = LD4(p, 4 * H * W);
                float4 u3 = LD4(p, 6 * H * W);
                float4 v0 = LD4(p, W);
                float4 v1 = LD4(p, W + 2 * H * W);
                float4 v2 = LD4(p, W + 4 * H * W);
                float4 v3 = LD4(p, W + 6 * H * W);
                FM4(u0, v0); FM4(u1, v1); FM4(u2, v2); FM4(u3, v3);
                FM4(a0, u0); FM4(a1, u1); FM4(a2, u2); FM4(a3, u3);
            }
            p += 2 * W;
        }
        if (ry <= ye && act) {
            float4 v0 = LD4(p, 0);
            float4 v1 = LD4(p, 2 * H * W);
            float4 v2 = LD4(p, 4 * H * W);
            float4 v3 = LD4(p, 6 * H * W);
            FM4(a0, v0); FM4(a1, v1); FM4(a2, v2); FM4(a3, v3);
        }

        // flush: load step s holds plane 2s+h
        *(float4*)(cw + (0 + h) * CMW + 4 * li) = a0;
        *(float4*)(cw + (2 + h) * CMW + 4 * li) = a1;
        *(float4*)(cw + (4 + h) * CMW + 4 * li) = a2;
        *(float4*)(cw + (6 + h) * CMW + 4 * li) = a3;
        __syncwarp();

        // reduce: pad-aware init (padded bins compete with 0; empty segment
        // implies padded -> init 0, matching the reference's isfinite->0)
        bool pady = (ph * psy < pad0y) | ((ph + 1) * psy > pad0y + leny);
        float init0 = (padx0 | pady) ? 0.0f : -INFINITY;
        float init1 = (padx1 | pady) ? 0.0f : -INFINITY;
        float m0 = 0.0f, m1 = 0.0f;
        switch (psx) {                    // warp-uniform, psx <= 10
#define SCASE(P) case P: m0 = segmax<P>(rp0, i00, i01, init0); \
                         if (r1) m1 = segmax<P>(rp1, i10, i11, init1); break;
            SCASE(1) SCASE(2) SCASE(3) SCASE(4) SCASE(5)
            SCASE(6) SCASE(7) SCASE(8) SCASE(9) SCASE(10)
#undef SCASE
        }
        out[o0 + ph * POOL] = m0;
        if (r1) out[o1 + ph * POOL] = m1;
        __syncwarp();
    }
#undef FM4
#undef LD4
}

extern "C" void kernel_launch(void* const* d_in, const int* in_sizes, int n_in,
                              void* d_out, int out_size) {
    const float* feat = (const float*)d_in[0];
    const float* rois = (const float*)d_in[1];
    float* out = (float*)d_out;

    const int C = 256;
    int N = in_sizes[1] / 5;

    int total = N * C * POOL * POOL;
    int write_bid = (out_size >= total + N) ? 1 : 0;

    dim3 grid(TPR / WPB, N);              // 16 x N blocks
    roipool_kernel<<<grid, 32 * WPB>>>(feat, rois, out, N, C, write_bid);
}

// round 15
// speedup vs baseline: 1.0935x; 1.0935x over previous
#include <cuda_runtime.h>
#include <math.h>

#define POOL 7
#define ROI_SCALE 0.0625f
#define WPB 8        // warps per block
#define CH  8        // channels per warp
#define NGR 32       // channel groups = C/CH
#define CMW 72       // smem row pitch: 4 front border + 64 cols + 4 back
#define TPR (NGR * POOL)  // warp-tasks per ROI = 224

// Unguarded unrolled segment max: borders are pre-filled with -INF so every
// in-range smem cell outside the valid crop window reads as -INF.
template<int PSX>
__device__ __forceinline__ float segmax(const float* rp, float init) {
    float mm = init;
    #pragma unroll
    for (int i = 0; i < PSX; ++i) mm = fmaxf(mm, rp[i]);
    return mm;
}

// grid = (TPR/WPB, N) = (28, N). Block owns one ROI (geometry decoded once by
// thread 0 into smem). Warp task = (8-channel group, row-bin). Lanes:
// h=lane>>4 picks plane parity, li=lane&15 covers 64 cols as float4 ->
// 4 LDG.128/row for 8 planes, 2-row unrolled (8 LDG.128 in flight).
// Per bin: flush 4xSTS.128 at +4 offset into 2.25KB/warp smem, fill -INF
// borders, then each lane reduces 2 of the 56 (ch,pw) outputs with a
// fully-unrolled predicate-free segmented max (psx warp-uniform).
__global__ __launch_bounds__(32 * WPB, 6)
void roipool_kernel(const float* __restrict__ feat,
                    const float* __restrict__ rois,
                    float* __restrict__ out,
                    int N, int C, int write_bid) {
    __shared__ float cm[WPB][CH * CMW];
    __shared__ int g[10];   // b,px,py,qx, lenx,leny, psx,psy, pad0x,pad0y
    const int H = 64, W = 64;

    int n = blockIdx.y;

    // Fused second output of the reference tuple: batch ids as floats.
    if (write_bid && blockIdx.x == 0 && blockIdx.y == 0 && threadIdx.x < N) {
        out[N * C * POOL * POOL + threadIdx.x] =
            (float)((int)rois[threadIdx.x * 5]);
    }

    if (threadIdx.x == 0) {
        const float* r = rois + n * 5;
        // jnp.round = round-half-to-even = __float2int_rn
        int px = __float2int_rn(r[1] * ROI_SCALE);
        int py = __float2int_rn(r[2] * ROI_SCALE);
        int qx = __float2int_rn(r[3] * ROI_SCALE);
        int qy = __float2int_rn(r[4] * ROI_SCALE);
        int lenx = max(qx - px + 1, 1);
        int leny = max(qy - py + 1, 1);
        int psx  = (lenx + POOL - 1) / POOL;
        int psy  = (leny + POOL - 1) / POOL;
        g[0] = (int)r[0];
        g[1] = px; g[2] = py; g[3] = qx;
        g[4] = lenx; g[5] = leny;
        g[6] = psx; g[7] = psy;
        g[8] = (psx * POOL - lenx) / 2;
        g[9] = (psy * POOL - leny) / 2;
    }
    __syncthreads();

    int warp = threadIdx.x >> 5;
    int lane = threadIdx.x & 31;
    int task = blockIdx.x * WPB + warp;   // 0..TPR-1
    int cg   = task & (NGR - 1);          // channel group (8 channels)
    int ph   = task >> 5;                 // row bin 0..6

    // --- minimal prologue for the mainloop ---
    int psy = g[7], pad0y = g[9], leny = g[5];
    int ys = max(0, ph * psy - pad0y);
    int ye = min(leny - 1, (ph + 1) * psy - 1 - pad0y);
    bool empty = ys > ye;                 // fully zero-padded row bin

    if (!empty) {
        int h  = lane >> 4;               // plane parity
        int li = lane & 15;               // float4 column index
        int px4 = g[1] & ~3;              // 16B-aligned load base
        bool act = (px4 + 4 * li) <= g[3];

        const float* p = feat
            + (unsigned)((g[0] * C + cg * CH + h) * (H * W))
            + (unsigned)((g[2] + ys) * W + px4 + 4 * li);

        float4 a0 = make_float4(-INFINITY, -INFINITY, -INFINITY, -INFINITY);
        float4 a1 = a0, a2 = a0, a3 = a0;

#define FM4(d, s) d.x = fmaxf(d.x, s.x); d.y = fmaxf(d.y, s.y); \
                  d.z = fmaxf(d.z, s.z); d.w = fmaxf(d.w, s.w)
#define LD4(q, off) __ldg((const float4*)((q) + (off)))
        int ry = ys;
        for (; ry + 1 <= ye; ry += 2) {   // 8 LDG.128 in flight
            if (act) {
                float4 u0 = LD4(p, 0);
                float4 u1 = LD4(p, 2 * H * W);
                float4 u2 = LD4(p, 4 * H * W);
                float4 u3 = LD4(p, 6 * H * W);
                float4 v0 = LD4(p, W);
                float4 v1 = LD4(p, W + 2 * H * W);
                float4 v2 = LD4(p, W + 4 * H * W);
                float4 v3 = LD4(p, W + 6 * H * W);
                FM4(u0, v0); FM4(u1, v1); FM4(u2, v2); FM4(u3, v3);
                FM4(a0, u0); FM4(a1, u1); FM4(a2, u2); FM4(a3, u3);
            }
            p += 2 * W;
        }
        if (ry <= ye && act) {
            float4 v0 = LD4(p, 0);
            float4 v1 = LD4(p, 2 * H * W);
            float4 v2 = LD4(p, 4 * H * W);
            float4 v3 = LD4(p, 6 * H * W);
            FM4(a0, v0); FM4(a1, v1); FM4(a2, v2); FM4(a3, v3);
        }
#undef FM4
#undef LD4

        // flush at +4 offset: load step s holds plane 2s+h
        float* cw = cm[warp];
        *(float4*)(cw + (0 + h) * CMW + 4 + 4 * li) = a0;
        *(float4*)(cw + (2 + h) * CMW + 4 + 4 * li) = a1;
        *(float4*)(cw + (4 + h) * CMW + 4 + 4 * li) = a2;
        *(float4*)(cw + (6 + h) * CMW + 4 + 4 * li) = a3;

        // -INF borders: lanes 0..7 fill left [0, 4+dpx) of channel=lane,
        // lanes 8..15 fill right [4+dpx+lenx, +4) of channel=lane-8.
        {
            int dpx = g[1] - px4;
            int lenx = g[4];
            if (lane < CH) {
                float* rowp = cw + lane * CMW;
                #pragma unroll
                for (int i = 0; i < 7; ++i)
                    if (i < 4 + dpx) rowp[i] = -INFINITY;
            } else if (lane < 2 * CH) {
                float* rowp = cw + (lane - CH) * CMW + 4 + dpx + lenx;
                #pragma unroll
                for (int i = 0; i < 4; ++i) rowp[i] = -INFINITY;
            }
        }
        __syncwarp();
    }

    // --- epilogue: reduce roles computed here (not live across mainloop) ---
    int lenx = g[4], psx = g[6], pad0x = g[8];
    int dpx = g[1] & 3;                   // px - px4
    bool pady = (ph * psy < pad0y) | ((ph + 1) * psy > pad0y + leny);

    // Each lane owns 2 of the CH*POOL = 56 (ch,pw) outputs: lane and lane+32.
    int ch0 = lane / POOL, pw0 = lane - ch0 * POOL;   // const-div -> mul
    int bi1 = lane + 32;
    int ch1 = bi1 / POOL, pw1 = bi1 - ch1 * POOL;
    bool r1 = bi1 < CH * POOL;
    int ob = (n * C + cg * CH) * (POOL * POOL) + ph * POOL;
    int o0 = ob + ch0 * (POOL * POOL) + pw0;
    int o1 = ob + ch1 * (POOL * POOL) + pw1;

    if (empty) {
        out[o0] = 0.0f;
        if (r1) out[o1] = 0.0f;
        return;
    }

    const float* cw = cm[warp];
    bool padx0 = (pw0 * psx < pad0x) | ((pw0 + 1) * psx > pad0x + lenx);
    bool padx1 = (pw1 * psx < pad0x) | ((pw1 + 1) * psx > pad0x + lenx);
    float init0 = (padx0 | pady) ? 0.0f : -INFINITY;
    float init1 = (padx1 | pady) ? 0.0f : -INFINITY;
    const float* rp0 = cw + ch0 * CMW + 4 + dpx + pw0 * psx - pad0x;
    const float* rp1 = cw + ch1 * CMW + 4 + dpx + pw1 * psx - pad0x;

    float m0 = 0.0f, m1 = 0.0f;
    switch (psx) {                        // warp-uniform, psx <= 10
#define SCASE(P) case P: m0 = segmax<P>(rp0, init0); \
                         if (r1) m1 = segmax<P>(rp1, init1); break;
        SCASE(1) SCASE(2) SCASE(3) SCASE(4) SCASE(5)
        SCASE(6) SCASE(7) SCASE(8) SCASE(9) SCASE(10)
#undef SCASE
    }
    out[o0] = m0;
    if (r1) out[o1] = m1;
}

extern "C" void kernel_launch(void* const* d_in, const int* in_sizes, int n_in,
                              void* d_out, int out_size) {
    const float* feat = (const float*)d_in[0];
    const float* rois = (const float*)d_in[1];
    float* out = (float*)d_out;

    const int C = 256;
    int N = in_sizes[1] / 5;

    int total = N * C * POOL * POOL;
    int write_bid = (out_size >= total + N) ? 1 : 0;

    dim3 grid(TPR / WPB, N);              // 28 x N blocks
    roipool_kernel<<<grid, 32 * WPB>>>(feat, rois, out, N, C, write_bid);
}

// round 16
// speedup vs baseline: 1.1064x; 1.0118x over previous
#include <cuda_runtime.h>
#include <math.h>

#define POOL 7
#define ROI_SCALE 0.0625f
#define WPB 8        // warps per block
#define CH  16       // channels per warp
#define NGR 16       // channel groups = C/CH
#define CMW 68       // smem row pitch in floats (16B-aligned)
#define TPR (NGR * POOL)  // warp-tasks per ROI = 112

// grid = (TPR/WPB, N) = (14, N). Block owns one ROI (geometry decoded once by
// thread 0 into smem). Warp task = (16-channel group, row-bin). Lanes:
// h=lane>>4 picks plane parity, li=lane&15 covers 64 cols as float4; load
// step s = plane 2s+h -> 8 LDG.128 in flight per row for all 16 planes.
// Per bin: flush 8xSTS.128 to 4.25KB/warp smem; each lane reduces 4 of the
// 112 (ch,pw) outputs via the x-direction segmented max.
__global__ __launch_bounds__(32 * WPB, 4)
void roipool_kernel(const float* __restrict__ feat,
                    const float* __restrict__ rois,
                    float* __restrict__ out,
                    int N, int C, int write_bid) {
    __shared__ float cm[WPB][CH * CMW];
    __shared__ int g[10];   // b,px,py,qx, lenx,leny, psx,psy, pad0x,pad0y
    const int H = 64, W = 64;

    int n = blockIdx.y;

    // Fused second output of the reference tuple: batch ids as floats.
    if (write_bid && blockIdx.x == 0 && blockIdx.y == 0 && threadIdx.x < N) {
        out[N * C * POOL * POOL + threadIdx.x] =
            (float)((int)rois[threadIdx.x * 5]);
    }

    if (threadIdx.x == 0) {
        const float* r = rois + n * 5;
        // jnp.round = round-half-to-even = __float2int_rn
        int px = __float2int_rn(r[1] * ROI_SCALE);
        int py = __float2int_rn(r[2] * ROI_SCALE);
        int qx = __float2int_rn(r[3] * ROI_SCALE);
        int qy = __float2int_rn(r[4] * ROI_SCALE);
        int lenx = max(qx - px + 1, 1);
        int leny = max(qy - py + 1, 1);
        int psx  = (lenx + POOL - 1) / POOL;
        int psy  = (leny + POOL - 1) / POOL;
        g[0] = (int)r[0];
        g[1] = px; g[2] = py; g[3] = qx;
        g[4] = lenx; g[5] = leny;
        g[6] = psx; g[7] = psy;
        g[8] = (psx * POOL - lenx) / 2;
        g[9] = (psy * POOL - leny) / 2;
    }
    __syncthreads();

    int warp = threadIdx.x >> 5;
    int lane = threadIdx.x & 31;
    int task = blockIdx.x * WPB + warp;   // 0..TPR-1
    int cg   = task & (NGR - 1);          // channel group (16 channels)
    int ph   = task >> 4;                 // row bin 0..6

    // --- minimal prologue for the mainloop ---
    int psy = g[7], pad0y = g[9], leny = g[5];
    int ys = max(0, ph * psy - pad0y);
    int ye = min(leny - 1, (ph + 1) * psy - 1 - pad0y);
    bool empty = ys > ye;                 // fully zero-padded row bin

    if (!empty) {
        int h  = lane >> 4;               // plane parity
        int li = lane & 15;               // float4 column index
        int px4 = g[1] & ~3;              // 16B-aligned load base
        bool act = (px4 + 4 * li) <= g[3];

        const float* p = feat
            + (unsigned)((g[0] * C + cg * CH + h) * (H * W))
            + (unsigned)((g[2] + ys) * W + px4 + 4 * li);

        float4 a0 = make_float4(-INFINITY, -INFINITY, -INFINITY, -INFINITY);
        float4 a1 = a0, a2 = a0, a3 = a0, a4 = a0, a5 = a0, a6 = a0, a7 = a0;

#define FM4(d, s) d.x = fmaxf(d.x, s.x); d.y = fmaxf(d.y, s.y); \
                  d.z = fmaxf(d.z, s.z); d.w = fmaxf(d.w, s.w)
#define LD4(q, off) __ldg((const float4*)((q) + (off)))
        for (int ry = ys; ry <= ye; ++ry) {   // 8 LDG.128 in flight per row
            if (act) {
                float4 v0 = LD4(p, 0);
                float4 v1 = LD4(p, 2 * H * W);
                float4 v2 = LD4(p, 4 * H * W);
                float4 v3 = LD4(p, 6 * H * W);
                float4 v4 = LD4(p, 8 * H * W);
                float4 v5 = LD4(p, 10 * H * W);
                float4 v6 = LD4(p, 12 * H * W);
                float4 v7 = LD4(p, 14 * H * W);
                FM4(a0, v0); FM4(a1, v1); FM4(a2, v2); FM4(a3, v3);
                FM4(a4, v4); FM4(a5, v5); FM4(a6, v6); FM4(a7, v7);
            }
            p += W;
        }
#undef FM4
#undef LD4

        // flush: load step s holds plane 2s+h
        float* cw = cm[warp];
        *(float4*)(cw + (0 + h) * CMW + 4 * li)  = a0;
        *(float4*)(cw + (2 + h) * CMW + 4 * li)  = a1;
        *(float4*)(cw + (4 + h) * CMW + 4 * li)  = a2;
        *(float4*)(cw + (6 + h) * CMW + 4 * li)  = a3;
        *(float4*)(cw + (8 + h) * CMW + 4 * li)  = a4;
        *(float4*)(cw + (10 + h) * CMW + 4 * li) = a5;
        *(float4*)(cw + (12 + h) * CMW + 4 * li) = a6;
        *(float4*)(cw + (14 + h) * CMW + 4 * li) = a7;
        __syncwarp();
    }

    // --- epilogue: each lane reduces 4 of the CH*POOL = 112 outputs ---
    int lenx = g[4], psx = g[6], pad0x = g[8];
    int dpx = g[1] & 3;                   // px - px4
    bool pady = (ph * psy < pad0y) | ((ph + 1) * psy > pad0y + leny);
    int ob = (n * C + cg * CH) * (POOL * POOL) + ph * POOL;
    const float* cw = cm[warp];

    #pragma unroll
    for (int k = 0; k < 4; ++k) {
        int bi = lane + 32 * k;
        if (bi >= CH * POOL) break;       // only k=3 partially masked
        int ch = bi / POOL;               // const-div -> mul
        int pw = bi - ch * POOL;
        int o  = ob + ch * (POOL * POOL) + pw;

        if (empty) { out[o] = 0.0f; continue; }

        int x0 = pw * psx - pad0x;
        int i0 = max(0, -x0);
        int i1 = min(psx, lenx - x0);
        const float* rp = cw + ch * CMW + x0 + dpx;
        float mm = -INFINITY;
        for (int i = i0; i < i1; ++i) mm = fmaxf(mm, rp[i]);
        bool padx = (pw * psx < pad0x) | ((pw + 1) * psx > pad0x + lenx);
        if (padx | pady) mm = fmaxf(mm, 0.0f);
        if (!isfinite(mm)) mm = 0.0f;     // fully-padded bin -> 0
        out[o] = mm;
    }
}

extern "C" void kernel_launch(void* const* d_in, const int* in_sizes, int n_in,
                              void* d_out, int out_size) {
    const float* feat = (const float*)d_in[0];
    const float* rois = (const float*)d_in[1];
    float* out = (float*)d_out;

    const int C = 256;
    int N = in_sizes[1] / 5;

    int total = N * C * POOL * POOL;
    int write_bid = (out_size >= total + N) ? 1 : 0;

    dim3 grid(TPR / WPB, N);              // 14 x N blocks
    roipool_kernel<<<grid, 32 * WPB>>>(feat, rois, out, N, C, write_bid);
}